// round 9
// baseline (speedup 1.0000x reference)
#include <cuda_runtime.h>

#define BB 4
#define CC 128
#define NN 4096
#define OC 256
#define KNN 10
#define NT 32   // number of 128-wide column tiles per row

typedef unsigned long long u64;

// Packed f32x2 helpers (sm_103a: SASS FFMA2, only reachable via PTX)
#define FMA_F32X2(d, a, b, c) \
    asm("fma.rn.f32x2 %0, %1, %2, %3;" : "=l"(d) : "l"(a), "l"(b), "l"(c))
#define PACK_F32X2(out, lo, hi) \
    asm("mov.b64 %0, {%1, %2};" : "=l"(out) : "f"(lo), "f"(hi))
#define UNPACK_F32X2(lo, hi, in) \
    asm("mov.b64 {%0, %1}, %2;" : "=f"(lo), "=f"(hi) : "l"(in))

// Scratch (device globals — no allocation in kernel_launch)
static __device__ float g_pv[(size_t)BB * NN * NT * KNN];  // per-tile top-10 values (21 MB)
static __device__ int   g_pi[(size_t)BB * NN * NT * KNN];  // per-tile top-10 indices (21 MB)
static __device__ float g_xx[BB * NN];
static __device__ float g_xT[(size_t)BB * NN * CC];      // x transposed [b][n][c]
static __device__ float g_mT[(size_t)BB * NN * CC];      // neighbor mean [b][n][c]
static __device__ int   g_idx[BB * NN * KNN];
static __device__ float g_Wcat[OC * 2 * CC];

// ---------------------------------------------------------------------------
// K1a: per-point squared norm  xx[b][n] = sum_c x[b][c][n]^2
__global__ void xx_kernel(const float* __restrict__ x) {
    int b = blockIdx.y;
    int n = blockIdx.x * blockDim.x + threadIdx.x;
    const float* xb = x + (size_t)b * CC * NN;
    float s = 0.f;
#pragma unroll 8
    for (int c = 0; c < CC; c++) {
        float v = xb[(size_t)c * NN + n];
        s += v * v;
    }
    g_xx[b * NN + n] = s;
}

// ---------------------------------------------------------------------------
// K1b: transpose x[b][c][n] -> xT[b][n][c]
__global__ void transpose_kernel(const float* __restrict__ x) {
    __shared__ float tile[32][33];
    int b  = blockIdx.z;
    int c0 = blockIdx.y * 32;
    int n0 = blockIdx.x * 32;
    const float* xb = x + (size_t)b * CC * NN;
    int tx = threadIdx.x, ty = threadIdx.y;  // (32, 8)
#pragma unroll
    for (int r = 0; r < 32; r += 8)
        tile[ty + r][tx] = xb[(size_t)(c0 + ty + r) * NN + n0 + tx];
    __syncthreads();
#pragma unroll
    for (int r = 0; r < 32; r += 8)
        g_xT[((size_t)b * NN + n0 + ty + r) * CC + c0 + tx] = tile[tx][ty + r];
}

// ---------------------------------------------------------------------------
// Shared 8x8-per-thread FFMA2 micro-kernel step
#define MICRO_FFMA2(ab, bb_)                                                 \
    do {                                                                     \
        float4 a0 = *(const float4*)((ab) + ty * 8);                         \
        float4 a1 = *(const float4*)((ab) + ty * 8 + 4);                     \
        float4 b0 = *(const float4*)((bb_) + tx * 8);                        \
        float4 b1 = *(const float4*)((bb_) + tx * 8 + 4);                    \
        u64 aa[8], bbp[4];                                                   \
        PACK_F32X2(aa[0], a0.x, a0.x); PACK_F32X2(aa[1], a0.y, a0.y);        \
        PACK_F32X2(aa[2], a0.z, a0.z); PACK_F32X2(aa[3], a0.w, a0.w);        \
        PACK_F32X2(aa[4], a1.x, a1.x); PACK_F32X2(aa[5], a1.y, a1.y);        \
        PACK_F32X2(aa[6], a1.z, a1.z); PACK_F32X2(aa[7], a1.w, a1.w);        \
        PACK_F32X2(bbp[0], b0.x, b0.y); PACK_F32X2(bbp[1], b0.z, b0.w);      \
        PACK_F32X2(bbp[2], b1.x, b1.y); PACK_F32X2(bbp[3], b1.z, b1.w);      \
        _Pragma("unroll")                                                    \
        for (int i = 0; i < 8; i++)                                          \
            _Pragma("unroll")                                                \
            for (int p = 0; p < 4; p++)                                      \
                FMA_F32X2(acc2[i][p], aa[i], bbp[p], acc2[i][p]);            \
    } while (0)

// ---------------------------------------------------------------------------
// Per-tile partial top-10: stage holds a 128x128 score tile (row-local x 129
// pitch).  2 threads per row scan 64 cols each (ascending col order; strict >
// insertion keeps lowest index on ties), then the even thread merges the pair
// (even thread covers lower columns, so it wins value ties) and stores the
// tile's exact per-row top-10 to g_pv/g_pi.
// Reuses `sm` (stage) for the odd-thread publish buffers after the scan.
__device__ __forceinline__ void tile_topk_store(
    float* sm, const float* stage, int b, int row_base, int col_base,
    int slot, int tid) {
    int r    = tid >> 1;
    int half = tid & 1;
    const float* src = stage + r * 129 + half * 64;

    const float NEG = -3.4028235e38f;
    float lv[KNN];
    int   li[KNN];
#pragma unroll
    for (int k = 0; k < KNN; k++) { lv[k] = NEG; li[k] = 0x7fffffff; }

#pragma unroll 4
    for (int c = 0; c < 64; c++) {
        float v = src[c];
        if (v > lv[KNN - 1]) {
            float cv = v; int ci = col_base + half * 64 + c;
#pragma unroll
            for (int k = 0; k < KNN; k++) {
                bool sw = cv > lv[k];
                float tv = sw ? lv[k] : cv;
                int   tq = sw ? li[k] : ci;
                lv[k] = sw ? cv : lv[k];
                li[k] = sw ? ci : li[k];
                cv = tv; ci = tq;
            }
        }
    }
    __syncthreads();  // done reading stage; safe to overwrite with publish buf

    float* mv = sm;                 // 256*KNN floats
    int*   mi = (int*)(sm + 256 * KNN);
    if (half) {
#pragma unroll
        for (int k = 0; k < KNN; k++) {
            mv[r * KNN + k] = lv[k];
            mi[r * KNN + k] = li[k];
        }
    }
    __syncthreads();

    if (!half) {
        float bvv[KNN]; int bii[KNN];
#pragma unroll
        for (int k = 0; k < KNN; k++) {
            bvv[k] = mv[r * KNN + k];
            bii[k] = mi[r * KNN + k];
        }
        size_t obase = (((size_t)b * NN + row_base + r) * NT + slot) * KNN;
        int ia = 0, ib = 0;
#pragma unroll
        for (int k = 0; k < KNN; k++) {
            // even thread (A) holds lower column indices -> wins value ties
            bool takeA = (ib >= KNN) || (ia < KNN && lv[ia] >= bvv[ib]);
            float ov = takeA ? lv[ia] : bvv[ib];
            int   oi = takeA ? li[ia] : bii[ib];
            ia += takeA; ib += !takeA;
            g_pv[obase + k] = ov;
            g_pi[obase + k] = oi;
        }
    }
    __syncthreads();  // publish buffer free before stage is reused
}

// ---------------------------------------------------------------------------
// K2: symmetric Gram + score + fused per-tile top-10.  No score matrix in DRAM.
#define GRAM_SMEM_BYTES (128 * 129 * 4)

__global__ void __launch_bounds__(256) gram_kernel(const float* __restrict__ x) {
    extern __shared__ float sm[];
    float* As = sm;              // [2][8][128]
    float* Bs = sm + 2 * 8 * 128;
    float* stage = sm;           // [128][129], reused after compute

    int b = blockIdx.y;
    int t = blockIdx.x;
    int ti = 0;
    while ((ti + 1) * 32 - (ti + 1) * ti / 2 <= t) ti++;
    int tj = ti + (t - (ti * 32 - ti * (ti - 1) / 2));
    int n0 = ti * 128, m0 = tj * 128;

    const float* xb = x + (size_t)b * CC * NN;
    int tid = threadIdx.x;
    int tx = tid % 16, ty = tid / 16;

    u64 acc2[8][4];
#pragma unroll
    for (int i = 0; i < 8; i++)
#pragma unroll
        for (int p = 0; p < 4; p++) acc2[i][p] = 0ull;

#pragma unroll
    for (int l = 0; l < 4; l++) {
        int e = tid + l * 256;
        int kk = e >> 7, col = e & 127;
        As[e] = xb[(size_t)kk * NN + n0 + col];
        Bs[e] = xb[(size_t)kk * NN + m0 + col];
    }
    __syncthreads();

    int buf = 0;
    for (int c0 = 0; c0 < CC; c0 += 8) {
        int nc = c0 + 8;
        float ra[4], rb[4];
        if (nc < CC) {
#pragma unroll
            for (int l = 0; l < 4; l++) {
                int e = tid + l * 256;
                int kk = e >> 7, col = e & 127;
                ra[l] = xb[(size_t)(nc + kk) * NN + n0 + col];
                rb[l] = xb[(size_t)(nc + kk) * NN + m0 + col];
            }
        }
#pragma unroll
        for (int kk = 0; kk < 8; kk++) {
            const float* ab = As + buf * 1024 + kk * 128;
            const float* bb = Bs + buf * 1024 + kk * 128;
            MICRO_FFMA2(ab, bb);
        }
        if (nc < CC) {
            int ob = buf ^ 1;
#pragma unroll
            for (int l = 0; l < 4; l++) {
                int e = tid + l * 256;
                As[ob * 1024 + e] = ra[l];
                Bs[ob * 1024 + e] = rb[l];
            }
            __syncthreads();
            buf = ob;
        }
    }

    // unpack accumulators
    float acc[8][8];
#pragma unroll
    for (int i = 0; i < 8; i++)
#pragma unroll
        for (int p = 0; p < 4; p++)
            UNPACK_F32X2(acc[i][2 * p], acc[i][2 * p + 1], acc2[i][p]);

    float xxm[8], xxn[8];
#pragma unroll
    for (int j = 0; j < 8; j++) xxm[j] = g_xx[b * NN + m0 + tx * 8 + j];
#pragma unroll
    for (int i = 0; i < 8; i++) xxn[i] = g_xx[b * NN + n0 + ty * 8 + i];

    __syncthreads();  // mainloop fully done; safe to overwrite As/Bs (stage)

    // direct tile: stage score[n][m] = 2*acc - xx[m], then partial top-10
#pragma unroll
    for (int i = 0; i < 8; i++)
#pragma unroll
        for (int j = 0; j < 8; j++)
            stage[(ty * 8 + i) * 129 + tx * 8 + j] = 2.f * acc[i][j] - xxm[j];
    __syncthreads();
    tile_topk_store(sm, stage, b, n0, m0, tj, tid);

    // mirror tile: stage score[m][n] = 2*acc - xx[n], then partial top-10
    if (ti != tj) {
#pragma unroll
        for (int i = 0; i < 8; i++)
#pragma unroll
            for (int j = 0; j < 8; j++)
                stage[(tx * 8 + j) * 129 + ty * 8 + i] = 2.f * acc[i][j] - xxn[i];
        __syncthreads();
        tile_topk_store(sm, stage, b, m0, n0, ti, tid);
    }
}

// ---------------------------------------------------------------------------
// K3: exact global top-10 from the 32 per-tile partial lists.
// One warp per row; lane = tile slot (each lane's list is sorted desc,
// lowest-index-on-tie).  10-round shuffle argmax merge with
// (value desc, index asc) tie-break = jax.lax.top_k.  Indices unique per row.
__global__ void __launch_bounds__(256) topk_final_kernel() {
    const unsigned FULL = 0xffffffffu;
    int gw   = (blockIdx.x * 256 + threadIdx.x) >> 5;
    int lane = threadIdx.x & 31;
    int b = gw >> 12;
    int n = gw & (NN - 1);
    size_t base = (((size_t)b * NN + n) * NT + lane) * KNN;

    const float NEG = -3.4028235e38f;
    float lv[KNN];
    int   li[KNN];
#pragma unroll
    for (int k = 0; k < KNN; k++) {
        lv[k] = g_pv[base + k];
        li[k] = g_pi[base + k];
    }

#pragma unroll
    for (int r = 0; r < KNN; r++) {
        float cv = lv[0]; int ci = li[0];
        float bv = cv;    int bi = ci;
#pragma unroll
        for (int off = 16; off; off >>= 1) {
            float ov = __shfl_xor_sync(FULL, bv, off);
            int   oi = __shfl_xor_sync(FULL, bi, off);
            if (ov > bv || (ov == bv && oi < bi)) { bv = ov; bi = oi; }
        }
        if (lane == r) g_idx[(b * NN + n) * KNN + r] = bi;
        if (bi == ci) {  // this lane won: pop head
#pragma unroll
            for (int k = 0; k < KNN - 1; k++) { lv[k] = lv[k + 1]; li[k] = li[k + 1]; }
            lv[KNN - 1] = NEG; li[KNN - 1] = 0x7fffffff;
        }
    }
}

// ---------------------------------------------------------------------------
// K4: neighbor mean  mT[b][n][c] = (1/K) sum_k xT[b][idx_k][c]
__global__ void gather_kernel() {
    int b = blockIdx.y;
    int n = blockIdx.x;
    int c = threadIdx.x;  // 128
    __shared__ int sidx[KNN];
    if (c < KNN) sidx[c] = g_idx[(b * NN + n) * KNN + c];
    __syncthreads();
    float acc = 0.f;
#pragma unroll
    for (int k = 0; k < KNN; k++)
        acc += g_xT[((size_t)b * NN + sidx[k]) * CC + c];
    g_mT[((size_t)b * NN + n) * CC + c] = acc / (float)KNN;
}

// ---------------------------------------------------------------------------
// K5: Wcat[o][c] = W1 for c<128, (W2 - W1) for c>=128
__global__ void wcat_kernel(const float* __restrict__ W) {
    int idx = blockIdx.x * 256 + threadIdx.x;
    int c = idx % (2 * CC);
    float v = W[idx];
    if (c >= CC) v -= W[idx - CC];
    g_Wcat[idx] = v;
}

// ---------------------------------------------------------------------------
// K6: out[b][o][n] = sum_c Wcat[o][c] * cat[c][n] + bias[o], FFMA2 mainloop.
__global__ void __launch_bounds__(256) out_gemm_kernel(
    const float* __restrict__ x, const float* __restrict__ bias,
    float* __restrict__ out) {
    __shared__ float As[2][1024];
    __shared__ float Bs[2][1024];

    int b  = blockIdx.z;
    int o0 = blockIdx.y * 128;
    int n0 = blockIdx.x * 128;
    const float* xb = x + (size_t)b * CC * NN;

    int tid = threadIdx.x;
    int tx = tid % 16, ty = tid / 16;

    u64 acc2[8][4];
#pragma unroll
    for (int i = 0; i < 8; i++)
#pragma unroll
        for (int p = 0; p < 4; p++) acc2[i][p] = 0ull;

    {
        float ra[4], rb[4];
#pragma unroll
        for (int l = 0; l < 4; l++) {
            int e  = tid + l * 256;
            int kk = e % 8;
            int i  = e / 8;
            ra[l] = g_Wcat[(o0 + i) * (2 * CC) + kk];
            rb[l] = g_mT[((size_t)b * NN + n0 + i) * CC + kk];
        }
#pragma unroll
        for (int l = 0; l < 4; l++) {
            int e = tid + l * 256;
            As[0][(e % 8) * 128 + e / 8] = ra[l];
            Bs[0][(e % 8) * 128 + e / 8] = rb[l];
        }
        __syncthreads();
    }

    int buf = 0;
    for (int c0 = 0; c0 < 2 * CC; c0 += 8) {
        int nc = c0 + 8;
        float ra[4], rb[4];
        bool rb_xlayout = false;
        if (nc < 2 * CC) {
#pragma unroll
            for (int l = 0; l < 4; l++) {
                int e  = tid + l * 256;
                int kk = e % 8;
                int i  = e / 8;
                ra[l] = g_Wcat[(o0 + i) * (2 * CC) + nc + kk];
            }
            if (nc < CC) {
#pragma unroll
                for (int l = 0; l < 4; l++) {
                    int e  = tid + l * 256;
                    int kk = e % 8;
                    int j  = e / 8;
                    rb[l] = g_mT[((size_t)b * NN + n0 + j) * CC + nc + kk];
                }
            } else {
                rb_xlayout = true;
#pragma unroll
                for (int l = 0; l < 4; l++) {
                    int e  = tid + l * 256;
                    int kk = e / 128;
                    int j  = e % 128;
                    rb[l] = xb[(size_t)(nc - CC + kk) * NN + n0 + j];
                }
            }
        }
#pragma unroll
        for (int kk = 0; kk < 8; kk++) {
            const float* ab = As[buf] + kk * 128;
            const float* bb = Bs[buf] + kk * 128;
            MICRO_FFMA2(ab, bb);
        }
        if (nc < 2 * CC) {
            int ob = buf ^ 1;
#pragma unroll
            for (int l = 0; l < 4; l++) {
                int e = tid + l * 256;
                As[ob][(e % 8) * 128 + e / 8] = ra[l];
            }
            if (!rb_xlayout) {
#pragma unroll
                for (int l = 0; l < 4; l++) {
                    int e = tid + l * 256;
                    Bs[ob][(e % 8) * 128 + e / 8] = rb[l];
                }
            } else {
#pragma unroll
                for (int l = 0; l < 4; l++) {
                    int e = tid + l * 256;
                    Bs[ob][(e / 128) * 128 + (e % 128)] = rb[l];
                }
            }
            __syncthreads();
            buf = ob;
        }
    }

    float acc[8][8];
#pragma unroll
    for (int i = 0; i < 8; i++)
#pragma unroll
        for (int p = 0; p < 4; p++)
            UNPACK_F32X2(acc[i][2 * p], acc[i][2 * p + 1], acc2[i][p]);

#pragma unroll
    for (int i = 0; i < 8; i++) {
        int o = o0 + ty * 8 + i;
        float bv = bias[o];
        float* orow = out + ((size_t)(b * OC + o)) * NN + n0 + tx * 8;
        float v[8];
#pragma unroll
        for (int j = 0; j < 8; j++) v[j] = acc[i][j] + bv;
        ((float4*)orow)[0] = make_float4(v[0], v[1], v[2], v[3]);
        ((float4*)orow)[1] = make_float4(v[4], v[5], v[6], v[7]);
    }
}

// ---------------------------------------------------------------------------
extern "C" void kernel_launch(void* const* d_in, const int* in_sizes, int n_in,
                              void* d_out, int out_size) {
    const float* x    = (const float*)d_in[0];
    const float* W    = (const float*)d_in[1];
    const float* bias = (const float*)d_in[2];
    float* out = (float*)d_out;

    cudaFuncSetAttribute(gram_kernel,
                         cudaFuncAttributeMaxDynamicSharedMemorySize,
                         GRAM_SMEM_BYTES);

    xx_kernel<<<dim3(NN / 256, BB), 256>>>(x);
    transpose_kernel<<<dim3(NN / 32, CC / 32, BB), dim3(32, 8)>>>(x);
    gram_kernel<<<dim3(528, BB), 256, GRAM_SMEM_BYTES>>>(x);
    topk_final_kernel<<<dim3(BB * NN / 8), 256>>>();
    gather_kernel<<<dim3(NN, BB), 128>>>();
    wcat_kernel<<<OC, 256>>>(W);
    out_gemm_kernel<<<dim3(NN / 128, OC / 128, BB), 256>>>(x, bias, out);
}